// round 14
// baseline (speedup 1.0000x reference)
#include <cuda_runtime.h>
#include <cuda_fp16.h>
#include <cstdint>

#define N_NODES 50000
#define N_EDGES 600000
#define F 128
#define F4 32
#define TILE 128
#define NT ((N_NODES + TILE - 1) / TILE)   // 391
#define GRID 148

// ---------------- scratch (static device globals) ----------------
__device__ int g_deg[N_NODES];
__device__ int g_off[N_NODES];
__device__ int g_total;
__device__ int g_rank[N_EDGES];
__device__ int g_srcs[N_EDGES];
__device__ __align__(16) __half g_xh[(size_t)N_NODES * F];  // fp16 copy of x
__device__ __align__(16) float g_h[(size_t)N_NODES * F];    // tf32-rounded mean-agg

// ---------------- static-init: resolve scratch symbol addresses once ----------------
namespace {
struct Aux {
    void* deg_ptr = nullptr;
    void* total_ptr = nullptr;
    Aux() {
        cudaGetSymbolAddress(&deg_ptr, g_deg);
        cudaGetSymbolAddress(&total_ptr, g_total);
    }
};
Aux g_aux;
}

// ---------------- helpers ----------------
__device__ __forceinline__ float rna_tf32(float v) {
    float r; asm("cvt.rna.tf32.f32 %0, %1;" : "=f"(r) : "f"(v)); return r;
}
__device__ __forceinline__ uint32_t smem_u32(const void* p) {
    uint32_t a;
    asm("{ .reg .u64 t; cvta.to.shared.u64 t, %1; cvt.u32.u64 %0, t; }" : "=r"(a) : "l"(p));
    return a;
}
#define CP_COMMIT() asm volatile("cp.async.commit_group;")
#define CP_WAIT2()  asm volatile("cp.async.wait_group 2;")

__device__ __forceinline__ void mma_tf32(float* c, uint32_t a0, uint32_t a1,
                                         uint32_t a2, uint32_t a3,
                                         uint32_t b0, uint32_t b1) {
    asm volatile(
        "mma.sync.aligned.m16n8k8.row.col.f32.tf32.tf32.f32 "
        "{%0,%1,%2,%3}, {%4,%5,%6,%7}, {%8,%9}, {%0,%1,%2,%3};"
        : "+f"(c[0]), "+f"(c[1]), "+f"(c[2]), "+f"(c[3])
        : "r"(a0), "r"(a1), "r"(a2), "r"(a3), "r"(b0), "r"(b1));
}

// ---------------- Kernel 0: x -> fp16 copy ----------------
__global__ void conv_kernel(const float4* __restrict__ x4) {
    int i = blockIdx.x * blockDim.x + threadIdx.x;
    if (i < N_NODES * F4) {
        float4 v = x4[i];
        __half2 h0 = __floats2half2_rn(v.x, v.y);
        __half2 h1 = __floats2half2_rn(v.z, v.w);
        uint2 u;
        u.x = *reinterpret_cast<uint32_t*>(&h0);
        u.y = *reinterpret_cast<uint32_t*>(&h1);
        ((uint2*)g_xh)[i] = u;
    }
}

// ---------------- Kernel 1: degree histogram + per-edge rank ----------------
__global__ void deg_kernel(const int4* __restrict__ dst4) {
    int i = blockIdx.x * blockDim.x + threadIdx.x;
    if (i < N_EDGES / 4) {
        int4 d = dst4[i];
        int4 r;
        r.x = atomicAdd(&g_deg[d.x], 1);
        r.y = atomicAdd(&g_deg[d.y], 1);
        r.z = atomicAdd(&g_deg[d.z], 1);
        r.w = atomicAdd(&g_deg[d.w], 1);
        ((int4*)g_rank)[i] = r;
    }
}

// ---------------- Kernel 2: block-scan offsets (multi-CTA; atomic block base) ----------------
__global__ void __launch_bounds__(256) offsets_kernel() {
    __shared__ int swarp[8];
    __shared__ int sbase;
    const int tid = threadIdx.x;
    const int i = blockIdx.x * 256 + tid;
    const int lane = tid & 31, w = tid >> 5;
    int d = (i < N_NODES) ? g_deg[i] : 0;
    int v = d;
    #pragma unroll
    for (int o = 1; o < 32; o <<= 1) {
        int t = __shfl_up_sync(0xFFFFFFFF, v, o);
        if (lane >= o) v += t;
    }
    if (lane == 31) swarp[w] = v;
    __syncthreads();
    if (tid == 0) {
        int run = 0;
        #pragma unroll
        for (int j = 0; j < 8; ++j) { int t = swarp[j]; swarp[j] = run; run += t; }
        sbase = atomicAdd(&g_total, run);
    }
    __syncthreads();
    if (i < N_NODES) g_off[i] = sbase + swarp[w] + v - d;   // exclusive prefix
}

// ---------------- Kernel 3: CSR scatter, atomic-free via rank ----------------
__global__ void scatter_kernel(const int4* __restrict__ src4,
                               const int4* __restrict__ dst4) {
    int i = blockIdx.x * blockDim.x + threadIdx.x;
    if (i < N_EDGES / 4) {
        int4 s = src4[i];
        int4 d = dst4[i];
        int4 r = ((const int4*)g_rank)[i];
        g_srcs[__ldg(&g_off[d.x]) + r.x] = s.x;
        g_srcs[__ldg(&g_off[d.y]) + r.y] = s.y;
        g_srcs[__ldg(&g_off[d.z]) + r.z] = s.z;
        g_srcs[__ldg(&g_off[d.w]) + r.w] = s.w;
    }
}

// ---------------- Kernel 4: mean aggregation (warp per node), fp16 gathers ----------------
// Lane owns 4 halves (uint2 = 8B); 32 lanes x 8B = 256B row. 8-wide MLP.
__global__ void agg_kernel() {
    int gw   = (blockIdx.x * blockDim.x + threadIdx.x) >> 5;
    int lane = threadIdx.x & 31;
    if (gw >= N_NODES) return;
    int beg = __ldg(&g_off[gw]);
    int cnt = __ldg(&g_deg[gw]);
    int end = beg + cnt;
    const uint2* __restrict__ xh = (const uint2*)g_xh;   // node*32 + lane

    float4 a0 = make_float4(0.f, 0.f, 0.f, 0.f);
    float4 a1 = a0;

    int e = beg;
    for (; e + 8 <= end; e += 8) {
        int s0 = __ldg(&g_srcs[e + 0]);
        int s1 = __ldg(&g_srcs[e + 1]);
        int s2 = __ldg(&g_srcs[e + 2]);
        int s3 = __ldg(&g_srcs[e + 3]);
        int s4 = __ldg(&g_srcs[e + 4]);
        int s5 = __ldg(&g_srcs[e + 5]);
        int s6 = __ldg(&g_srcs[e + 6]);
        int s7 = __ldg(&g_srcs[e + 7]);
        uint2 v0 = __ldg(&xh[(size_t)s0 * 32 + lane]);
        uint2 v1 = __ldg(&xh[(size_t)s1 * 32 + lane]);
        uint2 v2 = __ldg(&xh[(size_t)s2 * 32 + lane]);
        uint2 v3 = __ldg(&xh[(size_t)s3 * 32 + lane]);
        uint2 v4 = __ldg(&xh[(size_t)s4 * 32 + lane]);
        uint2 v5 = __ldg(&xh[(size_t)s5 * 32 + lane]);
        uint2 v6 = __ldg(&xh[(size_t)s6 * 32 + lane]);
        uint2 v7 = __ldg(&xh[(size_t)s7 * 32 + lane]);
        #define ACC(acc, u) do {                                             \
            float2 f0 = __half22float2(*reinterpret_cast<__half2*>(&(u).x)); \
            float2 f1 = __half22float2(*reinterpret_cast<__half2*>(&(u).y)); \
            (acc).x += f0.x; (acc).y += f0.y; (acc).z += f1.x; (acc).w += f1.y; } while (0)
        ACC(a0, v0); ACC(a1, v1); ACC(a0, v2); ACC(a1, v3);
        ACC(a0, v4); ACC(a1, v5); ACC(a0, v6); ACC(a1, v7);
    }
    if (e + 4 <= end) {
        int s0 = __ldg(&g_srcs[e + 0]);
        int s1 = __ldg(&g_srcs[e + 1]);
        int s2 = __ldg(&g_srcs[e + 2]);
        int s3 = __ldg(&g_srcs[e + 3]);
        uint2 v0 = __ldg(&xh[(size_t)s0 * 32 + lane]);
        uint2 v1 = __ldg(&xh[(size_t)s1 * 32 + lane]);
        uint2 v2 = __ldg(&xh[(size_t)s2 * 32 + lane]);
        uint2 v3 = __ldg(&xh[(size_t)s3 * 32 + lane]);
        ACC(a0, v0); ACC(a1, v1); ACC(a0, v2); ACC(a1, v3);
        e += 4;
    }
    for (; e < end; ++e) {
        int s = __ldg(&g_srcs[e]);
        uint2 v = __ldg(&xh[(size_t)s * 32 + lane]);
        ACC(a0, v);
    }
    #undef ACC
    float inv = 1.0f / (float)max(cnt, 1);
    float4 r;
    r.x = rna_tf32((a0.x + a1.x) * inv);
    r.y = rna_tf32((a0.y + a1.y) * inv);
    r.z = rna_tf32((a0.z + a1.z) * inv);
    r.w = rna_tf32((a0.w + a1.w) * inv);
    ((float4*)g_h)[(size_t)gw * F4 + lane] = r;
}

// ---------------- Kernel 5: fused tf32 mma.sync GEMM, K=256 ----------------
// D[50000,128] = [x | g_h] @ [Ws; Wn]  (+bias, relu)
// x enters the MMA RAW (HW tf32 truncation); h pre-rounded in agg; B RNA-rounded
// once at s==0.
// SMEM (floats): pad(128), B[k=256][n=128 rotated], 3x A chunk bufs (128x32 rotated)
//   B: element (k,n) at k*128 + ((n + 8k) & 127)
//   A: element (r,c) at r*32  + ((c + 4r) & 31)
#define B_F  128
#define A_F  (B_F + 32768)
#define SMEM_FLOATS (A_F + 3 * 4096)
#define SMEM_BYTES  (SMEM_FLOATS * 4)

__device__ __forceinline__ void prefetch_chunk(uint32_t sb, int tid, int bid, int s,
                                               const float* __restrict__ x) {
    int t = bid + (s >> 3) * GRID;
    if (t < NT) {
        int ck = s & 7;
        const float* base = (ck < 4) ? x : g_h;   // g_h resolved in device code
        int cf = (ck & 3) * 32;                 // float col offset within source row
        uint32_t dbase = sb + (A_F + (s % 3) * 4096) * 4;
        #pragma unroll
        for (int rep = 0; rep < 4; ++rep) {
            int i = tid + rep * 256;            // 0..1023 : (row, 16B-unit)
            int r = i >> 3, u = i & 7;
            int node = t * TILE + r;
            const float* g = base + (size_t)node * F + cf + u * 4;
            uint32_t dst = dbase + r * 128 + (((u + r) & 7) << 4);
            int sz = (node < N_NODES) ? 16 : 0;
            asm volatile("cp.async.cg.shared.global [%0], [%1], 16, %2;"
                         :: "r"(dst), "l"(g), "r"(sz));
        }
    }
    CP_COMMIT();
}

__global__ void __launch_bounds__(256, 1)
gemm_kernel(const float* __restrict__ x,
            const float* __restrict__ Ws,
            const float* __restrict__ Wn,
            const float* __restrict__ bias,
            float* __restrict__ out) {
    extern __shared__ float sm[];
    uint32_t sb = smem_u32(sm);
    const int tid = threadIdx.x;
    const int wid = tid >> 5, lane = tid & 31;
    const int gid = lane >> 2, tig = lane & 3;
    const int bid = blockIdx.x;
    const int m_base = (wid >> 2) * 64;        // warp rows [m_base, m_base+64)
    const int n_base = (wid & 3) * 32;         // warp cols [n_base, n_base+32)

    float2 bv[4];
    #pragma unroll
    for (int nt = 0; nt < 4; ++nt) {
        int n = n_base + nt * 8 + 2 * tig;
        bv[nt] = make_float2(__ldg(&bias[n]), __ldg(&bias[n + 1]));
    }

    // Load B = [Ws;Wn] (256x128) straight from inputs into rotated layout.
    for (int i = tid; i < 8192; i += 256) {
        int k = i >> 5, u = i & 31;
        const float* src = (k < 128) ? Ws + k * 128 + u * 4
                                     : Wn + (k - 128) * 128 + u * 4;
        uint32_t dst = sb + B_F * 4 + k * 512 + (((u + 2 * k) & 31) << 4);
        asm volatile("cp.async.cg.shared.global [%0], [%1], 16;"
                     :: "r"(dst), "l"(src));
    }
    CP_COMMIT();
    prefetch_chunk(sb, tid, bid, 0, x);
    prefetch_chunk(sb, tid, bid, 1, x);
    prefetch_chunk(sb, tid, bid, 2, x);

    const uint32_t* Bs = (const uint32_t*)(sm + B_F);
    const int ntile_cta = (bid < NT) ? ((NT - 1 - bid) / GRID + 1) : 0;
    const int nstream = ntile_cta * 8;

    float acc[4][4][4];
    #pragma unroll
    for (int mt = 0; mt < 4; ++mt)
        #pragma unroll
        for (int nt = 0; nt < 4; ++nt)
            #pragma unroll
            for (int q = 0; q < 4; ++q) acc[mt][nt][q] = 0.f;

    for (int s = 0; s < nstream; ++s) {
        CP_WAIT2();                 // chunk s (and B on first iter) landed
        __syncthreads();

        if (s == 0) {
            // ---- one-time RNA rounding of B in SMEM ----
            float4* Bp = (float4*)(sm + B_F);
            #pragma unroll
            for (int rep = 0; rep < 32; ++rep) {
                float4 v = Bp[tid + rep * 256];
                v.x = rna_tf32(v.x); v.y = rna_tf32(v.y);
                v.z = rna_tf32(v.z); v.w = rna_tf32(v.w);
                Bp[tid + rep * 256] = v;
            }
            __syncthreads();
        }

        const uint32_t* As = (const uint32_t*)(sm + A_F + (s % 3) * 4096);
        const int kg0 = (s & 7) * 32;     // global k base of this chunk

        #pragma unroll
        for (int ks = 0; ks < 4; ++ks) {
            const int k0 = ks * 8;
            uint32_t bf[4][2];
            #pragma unroll
            for (int nt = 0; nt < 4; ++nt) {
                int n  = n_base + nt * 8 + gid;
                int ka = kg0 + k0 + tig;
                int kb = ka + 4;
                bf[nt][0] = Bs[ka * 128 + ((n + 8 * ka) & 127)];
                bf[nt][1] = Bs[kb * 128 + ((n + 8 * kb) & 127)];
            }
            #pragma unroll
            for (int mt = 0; mt < 4; ++mt) {
                int r0 = m_base + mt * 16 + gid;
                int r1 = r0 + 8;
                int c0 = k0 + tig, c1 = c0 + 4;
                uint32_t a0 = As[r0 * 32 + ((c0 + 4 * r0) & 31)];
                uint32_t a1 = As[r1 * 32 + ((c0 + 4 * r1) & 31)];
                uint32_t a2 = As[r0 * 32 + ((c1 + 4 * r0) & 31)];
                uint32_t a3 = As[r1 * 32 + ((c1 + 4 * r1) & 31)];
                #pragma unroll
                for (int nt = 0; nt < 4; ++nt)
                    mma_tf32(acc[mt][nt], a0, a1, a2, a3, bf[nt][0], bf[nt][1]);
            }
        }
        __syncthreads();            // readers done before buffer reuse
        prefetch_chunk(sb, tid, bid, s + 3, x);

        if ((s & 7) == 7) {
            // ---- epilogue: bias + relu + store, reset acc ----
            const int tile = bid + (s >> 3) * GRID;
            const int rowb = tile * TILE;
            #pragma unroll
            for (int mt = 0; mt < 4; ++mt) {
                int r0 = rowb + m_base + mt * 16 + gid;
                int r1 = r0 + 8;
                #pragma unroll
                for (int nt = 0; nt < 4; ++nt) {
                    int n = n_base + nt * 8 + 2 * tig;
                    if (r0 < N_NODES) {
                        float2 v;
                        v.x = fmaxf(acc[mt][nt][0] + bv[nt].x, 0.f);
                        v.y = fmaxf(acc[mt][nt][1] + bv[nt].y, 0.f);
                        *(float2*)&out[(size_t)r0 * F + n] = v;
                    }
                    if (r1 < N_NODES) {
                        float2 v;
                        v.x = fmaxf(acc[mt][nt][2] + bv[nt].x, 0.f);
                        v.y = fmaxf(acc[mt][nt][3] + bv[nt].y, 0.f);
                        *(float2*)&out[(size_t)r1 * F + n] = v;
                    }
                    acc[mt][nt][0] = acc[mt][nt][1] = 0.f;
                    acc[mt][nt][2] = acc[mt][nt][3] = 0.f;
                }
            }
        }
    }
}

// ---------------- Launch ----------------
extern "C" void kernel_launch(void* const* d_in, const int* in_sizes, int n_in,
                              void* d_out, int out_size) {
    const float* x   = (const float*)d_in[0];
    const float* Ws  = (const float*)d_in[1];
    const float* Wn  = (const float*)d_in[2];
    const float* b   = (const float*)d_in[3];
    const int*   src = (const int*)d_in[4];
    const int*   dst = (const int*)d_in[5];
    float* out = (float*)d_out;

    cudaFuncSetAttribute(gemm_kernel,
                         cudaFuncAttributeMaxDynamicSharedMemorySize, SMEM_BYTES);

    // zero degree histogram + scan base via memset nodes (no kernel launch)
    cudaMemsetAsync(g_aux.deg_ptr, 0, N_NODES * sizeof(int), 0);
    cudaMemsetAsync(g_aux.total_ptr, 0, sizeof(int), 0);

    conv_kernel<<<(N_NODES * F4 + 255) / 256, 256>>>((const float4*)x);
    deg_kernel<<<(N_EDGES / 4 + 255) / 256, 256>>>((const int4*)dst);
    offsets_kernel<<<(N_NODES + 255) / 256, 256>>>();
    scatter_kernel<<<(N_EDGES / 4 + 255) / 256, 256>>>((const int4*)src, (const int4*)dst);
    agg_kernel<<<(N_NODES * 32 + 255) / 256, 256>>>();
    gemm_kernel<<<GRID, 256, SMEM_BYTES>>>(x, Ws, Wn, b, out);
}

// round 16
// speedup vs baseline: 1.3534x; 1.3534x over previous
#include <cuda_runtime.h>
#include <cstdint>

#define N_NODES 50000
#define N_EDGES 600000
#define F 128
#define F4 32
#define TILE 128
#define NT ((N_NODES + TILE - 1) / TILE)   // 391
#define GRID 148

// ---------------- scratch (static device globals) ----------------
__device__ int g_deg[N_NODES];
__device__ int g_off[N_NODES];
__device__ int g_total;
__device__ int g_rank[N_EDGES];
__device__ int g_srcs[N_EDGES];
__device__ __align__(16) float g_h[(size_t)N_NODES * F];    // tf32-rounded mean-agg

// ---------------- static-init: resolve scratch symbol addresses once ----------------
namespace {
struct Aux {
    void* deg_ptr = nullptr;
    void* total_ptr = nullptr;
    Aux() {
        cudaGetSymbolAddress(&deg_ptr, g_deg);
        cudaGetSymbolAddress(&total_ptr, g_total);
    }
};
Aux g_aux;
}

// ---------------- helpers ----------------
__device__ __forceinline__ float rna_tf32(float v) {
    float r; asm("cvt.rna.tf32.f32 %0, %1;" : "=f"(r) : "f"(v)); return r;
}
__device__ __forceinline__ uint32_t smem_u32(const void* p) {
    uint32_t a;
    asm("{ .reg .u64 t; cvta.to.shared.u64 t, %1; cvt.u32.u64 %0, t; }" : "=r"(a) : "l"(p));
    return a;
}
#define CP_COMMIT() asm volatile("cp.async.commit_group;")
#define CP_WAIT2()  asm volatile("cp.async.wait_group 2;")

__device__ __forceinline__ void mma_tf32(float* c, uint32_t a0, uint32_t a1,
                                         uint32_t a2, uint32_t a3,
                                         uint32_t b0, uint32_t b1) {
    asm volatile(
        "mma.sync.aligned.m16n8k8.row.col.f32.tf32.tf32.f32 "
        "{%0,%1,%2,%3}, {%4,%5,%6,%7}, {%8,%9}, {%0,%1,%2,%3};"
        : "+f"(c[0]), "+f"(c[1]), "+f"(c[2]), "+f"(c[3])
        : "r"(a0), "r"(a1), "r"(a2), "r"(a3), "r"(b0), "r"(b1));
}

// ---------------- Kernel 1: degree histogram + per-edge rank ----------------
__global__ void deg_kernel(const int4* __restrict__ dst4) {
    int i = blockIdx.x * blockDim.x + threadIdx.x;
    if (i < N_EDGES / 4) {
        int4 d = dst4[i];
        int4 r;
        r.x = atomicAdd(&g_deg[d.x], 1);
        r.y = atomicAdd(&g_deg[d.y], 1);
        r.z = atomicAdd(&g_deg[d.z], 1);
        r.w = atomicAdd(&g_deg[d.w], 1);
        ((int4*)g_rank)[i] = r;
    }
}

// ---------------- Kernel 2: block-scan offsets (multi-CTA; atomic block base) ----------------
__global__ void __launch_bounds__(256) offsets_kernel() {
    __shared__ int swarp[8];
    __shared__ int sbase;
    const int tid = threadIdx.x;
    const int i = blockIdx.x * 256 + tid;
    const int lane = tid & 31, w = tid >> 5;
    int d = (i < N_NODES) ? g_deg[i] : 0;
    int v = d;
    #pragma unroll
    for (int o = 1; o < 32; o <<= 1) {
        int t = __shfl_up_sync(0xFFFFFFFF, v, o);
        if (lane >= o) v += t;
    }
    if (lane == 31) swarp[w] = v;
    __syncthreads();
    if (tid == 0) {
        int run = 0;
        #pragma unroll
        for (int j = 0; j < 8; ++j) { int t = swarp[j]; swarp[j] = run; run += t; }
        sbase = atomicAdd(&g_total, run);
    }
    __syncthreads();
    if (i < N_NODES) g_off[i] = sbase + swarp[w] + v - d;   // exclusive prefix
}

// ---------------- Kernel 3: CSR scatter, atomic-free via rank ----------------
__global__ void scatter_kernel(const int4* __restrict__ src4,
                               const int4* __restrict__ dst4) {
    int i = blockIdx.x * blockDim.x + threadIdx.x;
    if (i < N_EDGES / 4) {
        int4 s = src4[i];
        int4 d = dst4[i];
        int4 r = ((const int4*)g_rank)[i];
        g_srcs[__ldg(&g_off[d.x]) + r.x] = s.x;
        g_srcs[__ldg(&g_off[d.y]) + r.y] = s.y;
        g_srcs[__ldg(&g_off[d.z]) + r.z] = s.z;
        g_srcs[__ldg(&g_off[d.w]) + r.w] = s.w;
    }
}

// ---------------- Kernel 4: mean aggregation (warp per node), 4-wide MLP (R10 form) ----------------
__global__ void agg_kernel(const float4* __restrict__ x4) {
    int gw   = (blockIdx.x * blockDim.x + threadIdx.x) >> 5;
    int lane = threadIdx.x & 31;
    if (gw >= N_NODES) return;
    int beg = __ldg(&g_off[gw]);
    int cnt = __ldg(&g_deg[gw]);
    int end = beg + cnt;
    float4 a0 = make_float4(0.f, 0.f, 0.f, 0.f);
    float4 a1 = a0, a2 = a0, a3 = a0;
    int e = beg;
    for (; e + 4 <= end; e += 4) {
        int s0 = __ldg(&g_srcs[e + 0]);
        int s1 = __ldg(&g_srcs[e + 1]);
        int s2 = __ldg(&g_srcs[e + 2]);
        int s3 = __ldg(&g_srcs[e + 3]);
        float4 v0 = x4[(size_t)s0 * F4 + lane];
        float4 v1 = x4[(size_t)s1 * F4 + lane];
        float4 v2 = x4[(size_t)s2 * F4 + lane];
        float4 v3 = x4[(size_t)s3 * F4 + lane];
        a0.x += v0.x; a0.y += v0.y; a0.z += v0.z; a0.w += v0.w;
        a1.x += v1.x; a1.y += v1.y; a1.z += v1.z; a1.w += v1.w;
        a2.x += v2.x; a2.y += v2.y; a2.z += v2.z; a2.w += v2.w;
        a3.x += v3.x; a3.y += v3.y; a3.z += v3.z; a3.w += v3.w;
    }
    for (; e < end; ++e) {
        int s = __ldg(&g_srcs[e]);
        float4 v = x4[(size_t)s * F4 + lane];
        a0.x += v.x; a0.y += v.y; a0.z += v.z; a0.w += v.w;
    }
    float inv = 1.0f / (float)max(cnt, 1);
    float4 r;
    r.x = rna_tf32((a0.x + a1.x + a2.x + a3.x) * inv);
    r.y = rna_tf32((a0.y + a1.y + a2.y + a3.y) * inv);
    r.z = rna_tf32((a0.z + a1.z + a2.z + a3.z) * inv);
    r.w = rna_tf32((a0.w + a1.w + a2.w + a3.w) * inv);
    ((float4*)g_h)[(size_t)gw * F4 + lane] = r;
}

// ---------------- Kernel 5: fused tf32 mma.sync GEMM, K=256 (R12 form) ----------------
// D[50000,128] = [x | g_h] @ [Ws; Wn]  (+bias, relu)
// x enters the MMA RAW (HW tf32 truncation); h pre-rounded in agg; B RNA-rounded
// once at s==0.
// SMEM (floats): pad(128), B[k=256][n=128 rotated], 3x A chunk bufs (128x32 rotated)
//   B: element (k,n) at k*128 + ((n + 8k) & 127)
//   A: element (r,c) at r*32  + ((c + 4r) & 31)
#define B_F  128
#define A_F  (B_F + 32768)
#define SMEM_FLOATS (A_F + 3 * 4096)
#define SMEM_BYTES  (SMEM_FLOATS * 4)

__device__ __forceinline__ void prefetch_chunk(uint32_t sb, int tid, int bid, int s,
                                               const float* __restrict__ x) {
    int t = bid + (s >> 3) * GRID;
    if (t < NT) {
        int ck = s & 7;
        const float* base = (ck < 4) ? x : g_h;   // g_h resolved in device code
        int cf = (ck & 3) * 32;                 // float col offset within source row
        uint32_t dbase = sb + (A_F + (s % 3) * 4096) * 4;
        #pragma unroll
        for (int rep = 0; rep < 4; ++rep) {
            int i = tid + rep * 256;            // 0..1023 : (row, 16B-unit)
            int r = i >> 3, u = i & 7;
            int node = t * TILE + r;
            const float* g = base + (size_t)node * F + cf + u * 4;
            uint32_t dst = dbase + r * 128 + (((u + r) & 7) << 4);
            int sz = (node < N_NODES) ? 16 : 0;
            asm volatile("cp.async.cg.shared.global [%0], [%1], 16, %2;"
                         :: "r"(dst), "l"(g), "r"(sz));
        }
    }
    CP_COMMIT();
}

__global__ void __launch_bounds__(256, 1)
gemm_kernel(const float* __restrict__ x,
            const float* __restrict__ Ws,
            const float* __restrict__ Wn,
            const float* __restrict__ bias,
            float* __restrict__ out) {
    extern __shared__ float sm[];
    uint32_t sb = smem_u32(sm);
    const int tid = threadIdx.x;
    const int wid = tid >> 5, lane = tid & 31;
    const int gid = lane >> 2, tig = lane & 3;
    const int bid = blockIdx.x;
    const int m_base = (wid >> 2) * 64;        // warp rows [m_base, m_base+64)
    const int n_base = (wid & 3) * 32;         // warp cols [n_base, n_base+32)

    float2 bv[4];
    #pragma unroll
    for (int nt = 0; nt < 4; ++nt) {
        int n = n_base + nt * 8 + 2 * tig;
        bv[nt] = make_float2(__ldg(&bias[n]), __ldg(&bias[n + 1]));
    }

    // Load B = [Ws;Wn] (256x128) straight from inputs into rotated layout.
    for (int i = tid; i < 8192; i += 256) {
        int k = i >> 5, u = i & 31;
        const float* src = (k < 128) ? Ws + k * 128 + u * 4
                                     : Wn + (k - 128) * 128 + u * 4;
        uint32_t dst = sb + B_F * 4 + k * 512 + (((u + 2 * k) & 31) << 4);
        asm volatile("cp.async.cg.shared.global [%0], [%1], 16;"
                     :: "r"(dst), "l"(src));
    }
    CP_COMMIT();
    prefetch_chunk(sb, tid, bid, 0, x);
    prefetch_chunk(sb, tid, bid, 1, x);
    prefetch_chunk(sb, tid, bid, 2, x);

    const uint32_t* Bs = (const uint32_t*)(sm + B_F);
    const int ntile_cta = (bid < NT) ? ((NT - 1 - bid) / GRID + 1) : 0;
    const int nstream = ntile_cta * 8;

    float acc[4][4][4];
    #pragma unroll
    for (int mt = 0; mt < 4; ++mt)
        #pragma unroll
        for (int nt = 0; nt < 4; ++nt)
            #pragma unroll
            for (int q = 0; q < 4; ++q) acc[mt][nt][q] = 0.f;

    for (int s = 0; s < nstream; ++s) {
        CP_WAIT2();                 // chunk s (and B on first iter) landed
        __syncthreads();

        if (s == 0) {
            // ---- one-time RNA rounding of B in SMEM ----
            float4* Bp = (float4*)(sm + B_F);
            #pragma unroll
            for (int rep = 0; rep < 32; ++rep) {
                float4 v = Bp[tid + rep * 256];
                v.x = rna_tf32(v.x); v.y = rna_tf32(v.y);
                v.z = rna_tf32(v.z); v.w = rna_tf32(v.w);
                Bp[tid + rep * 256] = v;
            }
            __syncthreads();
        }

        const uint32_t* As = (const uint32_t*)(sm + A_F + (s % 3) * 4096);
        const int kg0 = (s & 7) * 32;     // global k base of this chunk

        #pragma unroll
        for (int ks = 0; ks < 4; ++ks) {
            const int k0 = ks * 8;
            uint32_t bf[4][2];
            #pragma unroll
            for (int nt = 0; nt < 4; ++nt) {
                int n  = n_base + nt * 8 + gid;
                int ka = kg0 + k0 + tig;
                int kb = ka + 4;
                bf[nt][0] = Bs[ka * 128 + ((n + 8 * ka) & 127)];
                bf[nt][1] = Bs[kb * 128 + ((n + 8 * kb) & 127)];
            }
            #pragma unroll
            for (int mt = 0; mt < 4; ++mt) {
                int r0 = m_base + mt * 16 + gid;
                int r1 = r0 + 8;
                int c0 = k0 + tig, c1 = c0 + 4;
                uint32_t a0 = As[r0 * 32 + ((c0 + 4 * r0) & 31)];
                uint32_t a1 = As[r1 * 32 + ((c0 + 4 * r1) & 31)];
                uint32_t a2 = As[r0 * 32 + ((c1 + 4 * r0) & 31)];
                uint32_t a3 = As[r1 * 32 + ((c1 + 4 * r1) & 31)];
                #pragma unroll
                for (int nt = 0; nt < 4; ++nt)
                    mma_tf32(acc[mt][nt], a0, a1, a2, a3, bf[nt][0], bf[nt][1]);
            }
        }
        __syncthreads();            // readers done before buffer reuse
        prefetch_chunk(sb, tid, bid, s + 3, x);

        if ((s & 7) == 7) {
            // ---- epilogue: bias + relu + store, reset acc ----
            const int tile = bid + (s >> 3) * GRID;
            const int rowb = tile * TILE;
            #pragma unroll
            for (int mt = 0; mt < 4; ++mt) {
                int r0 = rowb + m_base + mt * 16 + gid;
                int r1 = r0 + 8;
                #pragma unroll
                for (int nt = 0; nt < 4; ++nt) {
                    int n = n_base + nt * 8 + 2 * tig;
                    if (r0 < N_NODES) {
                        float2 v;
                        v.x = fmaxf(acc[mt][nt][0] + bv[nt].x, 0.f);
                        v.y = fmaxf(acc[mt][nt][1] + bv[nt].y, 0.f);
                        *(float2*)&out[(size_t)r0 * F + n] = v;
                    }
                    if (r1 < N_NODES) {
                        float2 v;
                        v.x = fmaxf(acc[mt][nt][2] + bv[nt].x, 0.f);
                        v.y = fmaxf(acc[mt][nt][3] + bv[nt].y, 0.f);
                        *(float2*)&out[(size_t)r1 * F + n] = v;
                    }
                    acc[mt][nt][0] = acc[mt][nt][1] = 0.f;
                    acc[mt][nt][2] = acc[mt][nt][3] = 0.f;
                }
            }
        }
    }
}

// ---------------- Launch ----------------
extern "C" void kernel_launch(void* const* d_in, const int* in_sizes, int n_in,
                              void* d_out, int out_size) {
    const float* x   = (const float*)d_in[0];
    const float* Ws  = (const float*)d_in[1];
    const float* Wn  = (const float*)d_in[2];
    const float* b   = (const float*)d_in[3];
    const int*   src = (const int*)d_in[4];
    const int*   dst = (const int*)d_in[5];
    float* out = (float*)d_out;

    cudaFuncSetAttribute(gemm_kernel,
                         cudaFuncAttributeMaxDynamicSharedMemorySize, SMEM_BYTES);

    // zero degree histogram + scan base via memset nodes (no kernel launch)
    cudaMemsetAsync(g_aux.deg_ptr, 0, N_NODES * sizeof(int), 0);
    cudaMemsetAsync(g_aux.total_ptr, 0, sizeof(int), 0);

    deg_kernel<<<(N_EDGES / 4 + 255) / 256, 256>>>((const int4*)dst);
    offsets_kernel<<<(N_NODES + 255) / 256, 256>>>();
    scatter_kernel<<<(N_EDGES / 4 + 255) / 256, 256>>>((const int4*)src, (const int4*)dst);
    agg_kernel<<<(N_NODES * 32 + 255) / 256, 256>>>((const float4*)x);
    gemm_kernel<<<GRID, 256, SMEM_BYTES>>>(x, Ws, Wn, b, out);
}